// round 2
// baseline (speedup 1.0000x reference)
#include <cuda_runtime.h>

#define DPRED   84
#define NCLS    80
#define MAXB    8
#define MAXA    76725
#define NBINS   4096
#define NCH     (NBINS / 32)
#define KMAX    4096
#define KTARGET 1536
#define MAXDET  100
#define CONF_T  0.05f
#define IOU_T   0.5f
#define NT      512
#define NMS_SMEM (KMAX * 32)

// ---------------- device scratch (no allocation allowed) ----------------
// 8 floats per anchor: cx,cy,w,h,cls,conf,pad,pad  (aligned float4 pairs)
__device__ float4 g_boxes8[MAXB * MAXA * 2];
__device__ float  g_scores[MAXB * MAXA];      // conf if >= CONF_T else 0
__device__ int    g_hist[MAXB * NBINS];
__device__ float  g_thresh[MAXB];
__device__ int    g_cnt[MAXB];
__device__ int    g_cand[MAXB * KMAX];

// ---------------- decode: warp per anchor ----------------
__global__ void decode_kernel(const float* __restrict__ pred,
                              const float* __restrict__ anchors,
                              int B, int A) {
    int gw   = (blockIdx.x * blockDim.x + threadIdx.x) >> 5;
    int lane = threadIdx.x & 31;
    if (gw >= B * A) return;
    int a = gw % A;

    const float* row = pred + (size_t)gw * DPRED;
    float4 v = make_float4(-3.4e38f, -3.4e38f, -3.4e38f, -3.4e38f);
    if (lane < DPRED / 4)
        v = __ldg(reinterpret_cast<const float4*>(row) + lane);

    // per-lane argmax over class logits (j >= 4), first-occurrence ties
    float best = -3.4e38f;
    int   bi   = 1 << 30;
    float vv[4] = {v.x, v.y, v.z, v.w};
    int j0 = lane * 4;
#pragma unroll
    for (int t = 0; t < 4; t++) {
        int j = j0 + t;
        if (j >= 4 && vv[t] > best) { best = vv[t]; bi = j - 4; }
    }
#pragma unroll
    for (int off = 16; off; off >>= 1) {
        float ob = __shfl_down_sync(0xffffffffu, best, off);
        int   oi = __shfl_down_sync(0xffffffffu, bi, off);
        if (ob > best || (ob == best && oi < bi)) { best = ob; bi = oi; }
    }

    if (lane == 0) {
        float4 an = __ldg(reinterpret_cast<const float4*>(anchors) + a);
        float cx = v.x * 0.1f * an.z + an.x;
        float cy = v.y * 0.1f * an.w + an.y;
        float w  = expf(v.z * 0.2f) * an.z;
        float h  = expf(v.w * 0.2f) * an.w;
        float conf = 1.0f / (1.0f + expf(-best));
        g_boxes8[(size_t)gw * 2 + 0] = make_float4(cx, cy, w, h);
        g_boxes8[(size_t)gw * 2 + 1] = make_float4((float)bi, conf, 0.f, 0.f);
        g_scores[gw] = (conf >= CONF_T) ? conf : 0.0f;
    }
}

// ---------------- histogram over scores ----------------
__global__ void zero_hist_kernel(int n) {
    int i = blockIdx.x * blockDim.x + threadIdx.x;
    if (i < n) g_hist[i] = 0;
}

__global__ void hist_kernel(int A) {
    __shared__ int sh[NBINS];
    for (int i = threadIdx.x; i < NBINS; i += blockDim.x) sh[i] = 0;
    __syncthreads();
    int b = blockIdx.y;
    const float* sc = g_scores + (size_t)b * A;
    for (int i = blockIdx.x * blockDim.x + threadIdx.x; i < A;
         i += gridDim.x * blockDim.x) {
        float s = sc[i];
        if (s > 0.0f) {
            int bin = (int)(s * (float)NBINS);
            if (bin > NBINS - 1) bin = NBINS - 1;
            if (bin < 1) bin = 1;
            atomicAdd(&sh[bin], 1);
        }
    }
    __syncthreads();
    for (int i = threadIdx.x; i < NBINS; i += blockDim.x) {
        int vcount = sh[i];
        if (vcount) atomicAdd(&g_hist[b * NBINS + i], vcount);
    }
}

// ---------------- pick score threshold per batch ----------------
__global__ void thresh_kernel() {
    int b = blockIdx.x;
    __shared__ int sh[NBINS];
    __shared__ int csum[NCH];
    for (int i = threadIdx.x; i < NBINS; i += blockDim.x)
        sh[i] = g_hist[b * NBINS + i];
    __syncthreads();
    if (threadIdx.x < NCH) {
        int s = 0;
#pragma unroll
        for (int j = 0; j < 32; j++) s += sh[threadIdx.x * 32 + j];
        csum[threadIdx.x] = s;
    }
    __syncthreads();
    if (threadIdx.x == 0) {
        int cum = 0, binSel = NBINS, c = NCH;
        while (c > 1 && cum < KTARGET && cum + csum[c - 1] <= KMAX) {
            c--; cum += csum[c]; binSel = c * 32;
        }
        if (cum < KTARGET && c >= 1) {
            for (int bin = c * 32 - 1; bin >= (c - 1) * 32 && bin >= 1; --bin) {
                int hcnt = sh[bin];
                if (cum + hcnt > KMAX) break;
                cum += hcnt; binSel = bin;
                if (cum >= KTARGET) break;
            }
        }
        g_thresh[b] = (float)binSel / (float)NBINS;
        g_cnt[b]    = 0;
    }
}

// ---------------- compact candidates ----------------
__global__ void compact_kernel(int A) {
    int b = blockIdx.y;
    float th = g_thresh[b];
    const float* sc = g_scores + (size_t)b * A;
    for (int i = blockIdx.x * blockDim.x + threadIdx.x; i < A;
         i += gridDim.x * blockDim.x) {
        if (sc[i] > th) {
            int p = atomicAdd(&g_cnt[b], 1);
            if (p < KMAX) g_cand[b * KMAX + p] = i;
        }
    }
}

// ---------------- NMS: one block per batch ----------------
__global__ void __launch_bounds__(NT, 1)
nms_kernel(float* __restrict__ out, int A) {
    int b   = blockIdx.x;
    int tid = threadIdx.x;

    extern __shared__ char smraw[];
    unsigned long long* skey  = (unsigned long long*)smraw;   // KMAX
    float* sx1  = (float*)(skey + KMAX);
    float* sy1  = sx1 + KMAX;
    float* sx2  = sy1 + KMAX;
    float* sy2  = sx2 + KMAX;
    float* sar  = sy2 + KMAX;
    int*   scls = (int*)(sar + KMAX);

    __shared__ unsigned long long redk[NT / 32];
    __shared__ int reds[NT / 32];
    __shared__ unsigned long long bKey;
    __shared__ int bSlot;
    __shared__ int fallback;

    int cnt = g_cnt[b];
    bool overflow = (cnt > KMAX);
    if (cnt > KMAX) cnt = KMAX;

    for (int i = tid; i < cnt; i += NT) {
        int a = g_cand[b * KMAX + i];
        size_t base = ((size_t)b * A + a) * 2;
        float4 p0 = g_boxes8[base + 0];
        float4 p1 = g_boxes8[base + 1];
        float hw = 0.5f * p0.z, hh = 0.5f * p0.w;
        sx1[i] = p0.x - hw; sy1[i] = p0.y - hh;
        sx2[i] = p0.x + hw; sy2[i] = p0.y + hh;
        sar[i] = p0.z * p0.w;
        scls[i] = (int)p1.x;
        skey[i] = ((unsigned long long)__float_as_uint(p1.y) << 32) |
                  (unsigned)(0x7FFFFFFF - a);
    }
    if (tid == 0) fallback = overflow ? 1 : 0;
    __syncthreads();

    if (!fallback) {
        for (int d = 0; d < MAXDET; d++) {
            unsigned long long mk = 0; int ms = -1;
            for (int i = tid; i < cnt; i += NT) {
                unsigned long long k = skey[i];
                if (k > mk) { mk = k; ms = i; }
            }
#pragma unroll
            for (int off = 16; off; off >>= 1) {
                unsigned long long ok = __shfl_down_sync(0xffffffffu, mk, off);
                int os = __shfl_down_sync(0xffffffffu, ms, off);
                if (ok > mk) { mk = ok; ms = os; }
            }
            if ((tid & 31) == 0) { redk[tid >> 5] = mk; reds[tid >> 5] = ms; }
            __syncthreads();
            if (tid < 32) {
                unsigned long long k2 = (tid < NT / 32) ? redk[tid] : 0ull;
                int s2 = (tid < NT / 32) ? reds[tid] : -1;
#pragma unroll
                for (int off = 16; off; off >>= 1) {
                    unsigned long long ok = __shfl_down_sync(0xffffffffu, k2, off);
                    int os = __shfl_down_sync(0xffffffffu, s2, off);
                    if (ok > k2) { k2 = ok; s2 = os; }
                }
                if (tid == 0) { bKey = k2; bSlot = s2; }
            }
            __syncthreads();

            unsigned long long selKey = bKey;
            float selScore = __uint_as_float((unsigned)(selKey >> 32));
            int   sl = bSlot;
            if (selScore <= 0.0f) {
                // candidate pool exhausted before MAXDET selections:
                // pruning guarantee no longer holds -> exact fallback
                if (tid == 0) fallback = 1;
                __syncthreads();
                break;
            }
            float X1 = sx1[sl], Y1 = sy1[sl], X2 = sx2[sl], Y2 = sy2[sl];
            float AR = sar[sl];
            int   CL = scls[sl];

            if (tid == 0) {
                int a = 0x7FFFFFFF - (int)(selKey & 0xFFFFFFFFull);
                size_t base = ((size_t)b * A + a) * 2;
                float4 p0 = g_boxes8[base + 0];
                float4 p1 = g_boxes8[base + 1];
                float* o = out + ((size_t)b * MAXDET + d) * 6;
                o[0] = p0.x; o[1] = p0.y; o[2] = p0.z;
                o[3] = p0.w; o[4] = p1.x; o[5] = selScore;
            }
            for (int i = tid; i < cnt; i += NT) {
                if (i == sl) { skey[i] = 0; continue; }
                if (scls[i] == CL && skey[i] != 0) {
                    float iw = fminf(sx2[i], X2) - fmaxf(sx1[i], X1);
                    float ih = fminf(sy2[i], Y2) - fmaxf(sy1[i], Y1);
                    if (iw > 0.0f && ih > 0.0f) {
                        float inter = iw * ih;
                        float iou = inter / (sar[i] + AR - inter + 1e-8f);
                        if (iou > IOU_T) skey[i] = 0;
                    }
                }
            }
            __syncthreads();
        }
    }
    __syncthreads();

    // ---------------- exact full-array fallback (normally unreachable) ----
    if (fallback) {
        float* sc = g_scores + (size_t)b * A;
        const float4* bx = g_boxes8 + (size_t)b * A * 2;
        for (int d = 0; d < MAXDET; d++) {
            unsigned long long mk = 0;
            for (int i = tid; i < A; i += NT) {
                unsigned long long k =
                    ((unsigned long long)__float_as_uint(sc[i]) << 32) |
                    (unsigned)(0x7FFFFFFF - i);
                if (k > mk) mk = k;
            }
#pragma unroll
            for (int off = 16; off; off >>= 1) {
                unsigned long long ok = __shfl_down_sync(0xffffffffu, mk, off);
                if (ok > mk) mk = ok;
            }
            if ((tid & 31) == 0) redk[tid >> 5] = mk;
            __syncthreads();
            if (tid < 32) {
                unsigned long long k2 = (tid < NT / 32) ? redk[tid] : 0ull;
#pragma unroll
                for (int off = 16; off; off >>= 1) {
                    unsigned long long ok = __shfl_down_sync(0xffffffffu, k2, off);
                    if (ok > k2) k2 = ok;
                }
                if (tid == 0) bKey = k2;
            }
            __syncthreads();
            unsigned long long selKey = bKey;
            int   a = 0x7FFFFFFF - (int)(selKey & 0xFFFFFFFFull);
            float selScore = __uint_as_float((unsigned)(selKey >> 32));
            float4 p0 = bx[(size_t)a * 2 + 0];
            float4 p1 = bx[(size_t)a * 2 + 1];
            float X1 = p0.x - 0.5f * p0.z, Y1 = p0.y - 0.5f * p0.w;
            float X2 = p0.x + 0.5f * p0.z, Y2 = p0.y + 0.5f * p0.w;
            float AR = p0.z * p0.w;
            int   CL = (int)p1.x;
            if (tid == 0) {
                float* o = out + ((size_t)b * MAXDET + d) * 6;
                o[0] = p0.x; o[1] = p0.y; o[2] = p0.z;
                o[3] = p0.w; o[4] = p1.x; o[5] = selScore;
            }
            __syncthreads();
            for (int i = tid; i < A; i += NT) {
                if (i == a) { sc[i] = 0.0f; continue; }
                if (sc[i] == 0.0f) continue;
                float4 q0 = bx[(size_t)i * 2 + 0];
                float4 q1 = bx[(size_t)i * 2 + 1];
                if ((int)q1.x == CL) {
                    float iw = fminf(q0.x + 0.5f * q0.z, X2) - fmaxf(q0.x - 0.5f * q0.z, X1);
                    float ih = fminf(q0.y + 0.5f * q0.w, Y2) - fmaxf(q0.y - 0.5f * q0.w, Y1);
                    if (iw > 0.0f && ih > 0.0f) {
                        float inter = iw * ih;
                        float iou = inter / (q0.z * q0.w + AR - inter + 1e-8f);
                        if (iou > IOU_T) sc[i] = 0.0f;
                    }
                }
            }
            __syncthreads();
        }
    }
}

// ---------------- launch ----------------
extern "C" void kernel_launch(void* const* d_in, const int* in_sizes, int n_in,
                              void* d_out, int out_size) {
    const float *pred, *anch;
    int s0 = in_sizes[0], s1 = in_sizes[1];
    if (s0 >= s1) {
        pred = (const float*)d_in[0]; anch = (const float*)d_in[1];
    } else {
        pred = (const float*)d_in[1]; anch = (const float*)d_in[0];
        int t = s0; s0 = s1; s1 = t;
    }
    int A = s1 / 4;
    int B = out_size / (MAXDET * 6);

    int totalWarps = B * A;
    decode_kernel<<<(totalWarps + 7) / 8, 256>>>(pred, anch, B, A);
    zero_hist_kernel<<<(B * NBINS + 255) / 256, 256>>>(B * NBINS);
    hist_kernel<<<dim3(32, B), 256>>>(A);
    thresh_kernel<<<B, 128>>>();
    compact_kernel<<<dim3(48, B), 256>>>(A);
    static int smem_set = 0;
    if (!smem_set) {
        cudaFuncSetAttribute(nms_kernel,
                             cudaFuncAttributeMaxDynamicSharedMemorySize, NMS_SMEM);
        smem_set = 1;
    }
    nms_kernel<<<B, NT, NMS_SMEM>>>((float*)d_out, A);
}